// round 5
// baseline (speedup 1.0000x reference)
#include <cuda_runtime.h>

#define HH 384
#define WW 384
#define HO 382
#define WO 382
#define RPAD 5
#define TH 20    /* 8 + 2 + 2*RPAD */
#define TW 44    /* 32 + 2 + 2*RPAD */

typedef unsigned long long u64;

// Constant layout (floats):
// [0,540)    cwp[27][20]: conv weight pairs, cwp[jj*20+2p] = (w[2p][jj], w[2p+1][jj])
// [540,558)  conv-bias pairs at 540+2p
// [560,632)  dcn (c0,c1) pairs: (dcn_w[o][0][k], dcn_w[o][1][k]) at 560+k*8+2o (k-major, padded)
// [632,659)  dcn c2: dcn_w[o][2][k] at 632+k*3+o
// [660,663)  dcn bias
__constant__ __align__(16) float CW[672];
__device__ __align__(16) float d_scratch[672];

__device__ __forceinline__ u64 ffma2(u64 a, u64 b, u64 c){
    u64 d; asm("fma.rn.f32x2 %0,%1,%2,%3;" : "=l"(d) : "l"(a), "l"(b), "l"(c)); return d;
}
__device__ __forceinline__ u64 mul2(u64 a, u64 b){
    u64 d; asm("mul.rn.f32x2 %0,%1,%2;" : "=l"(d) : "l"(a), "l"(b)); return d;
}
__device__ __forceinline__ u64 add2(u64 a, u64 b){
    u64 d; asm("add.rn.f32x2 %0,%1,%2;" : "=l"(d) : "l"(a), "l"(b)); return d;
}
__device__ __forceinline__ u64 rep2(float x){
    u64 r; asm("mov.b64 %0,{%1,%1};" : "=l"(r) : "f"(x)); return r;
}
__device__ __forceinline__ u64 pack2(float a, float b){
    u64 r; asm("mov.b64 %0,{%1,%2};" : "=l"(r) : "f"(a), "f"(b)); return r;
}
__device__ __forceinline__ float2 unpack2(u64 v){
    float2 f; asm("mov.b64 {%0,%1},%2;" : "=f"(f.x), "=f"(f.y) : "l"(v)); return f;
}
__device__ __forceinline__ u64 ldc64(int foff){
    return *reinterpret_cast<const u64*>(&CW[foff]);
}
__device__ __forceinline__ ulonglong2 ldc128(int foff){
    return *reinterpret_cast<const ulonglong2*>(&CW[foff]);
}

__global__ void repack(const float* __restrict__ cw, const float* __restrict__ cb,
                       const float* __restrict__ dw, const float* __restrict__ db,
                       float* __restrict__ s)
{
    int t = threadIdx.x;
    if (t < 486) { int o = t / 27, jj = t % 27; s[jj * 20 + o] = cw[t]; }
    else if (t < 504) { s[540 + (t - 486)] = cb[t - 486]; }
    else if (t < 531) {
        int i = t - 504; int o = i / 9, k = i % 9;
        s[560 + k * 8 + 2 * o + 0] = dw[o * 27 + 0 + k];
        s[560 + k * 8 + 2 * o + 1] = dw[o * 27 + 9 + k];
        s[632 + k * 3 + o]         = dw[o * 27 + 18 + k];
    }
    else if (t < 534) { s[660 + (t - 531)] = db[t - 531]; }
    else if (t < 543) { int k = t - 534; s[560 + k * 8 + 6] = 0.f; s[560 + k * 8 + 7] = 0.f; }
}

// One bilinear sample: computes packed (c0,c1) value v01 and scalar c2 value v2.
// INTERIOR: staged tile fully inside image => in-window implies in-image, no masks.
template<bool INTERIOR>
__device__ __forceinline__ void sample1(
    u64 off, float py0, float px0, int ybase, int xbase,
    const u64 (*tileP)[TW], const float (*tile2)[TW],
    const float* __restrict__ p0, const float* __restrict__ p1,
    const float* __restrict__ p2,
    u64& v01, float& v2)
{
    u64 pyx = add2(off, pack2(py0, px0));
    float2 q = unpack2(pyx);                       // (py, px)
    int y0 = __float2int_rd(q.x), x0 = __float2int_rd(q.y);
    float wy = q.x - (float)y0, wx = q.y - (float)x0;

    int ry = y0 - ybase, rx = x0 - xbase;
    bool inw = ((unsigned)ry < (unsigned)(TH - 1)) & ((unsigned)rx < (unsigned)(TW - 1));

    if (__builtin_expect(inw, 1)) {
        float a0, a1, b0, b1;
        if (INTERIOR) {
            a0 = 1.f - wy; a1 = wy; b0 = 1.f - wx; b1 = wx;
        } else {
            float vy0 = ((unsigned)y0       < (unsigned)HH) ? 1.f : 0.f;
            float vy1 = ((unsigned)(y0 + 1) < (unsigned)HH) ? 1.f : 0.f;
            float vx0 = ((unsigned)x0       < (unsigned)WW) ? 1.f : 0.f;
            float vx1 = ((unsigned)(x0 + 1) < (unsigned)WW) ? 1.f : 0.f;
            a0 = (1.f - wy) * vy0; a1 = wy * vy1;
            b0 = (1.f - wx) * vx0; b1 = wx * vx1;
        }
        float w00 = a0 * b0, w01 = a0 * b1, w10 = a1 * b0, w11 = a1 * b1;
        u64 t01 = mul2(tileP[ry][rx], rep2(w00));
        t01 = ffma2(tileP[ry][rx + 1],     rep2(w01), t01);
        t01 = ffma2(tileP[ry + 1][rx],     rep2(w10), t01);
        t01 = ffma2(tileP[ry + 1][rx + 1], rep2(w11), t01);
        v01 = t01;
        v2 = fmaf(tile2[ry + 1][rx + 1], w11,
             fmaf(tile2[ry + 1][rx],     w10,
             fmaf(tile2[ry][rx + 1],     w01, tile2[ry][rx] * w00)));
    } else {
        // Rare: outside staged window. Full masked global path.
        float vy0 = ((unsigned)y0       < (unsigned)HH) ? 1.f : 0.f;
        float vy1 = ((unsigned)(y0 + 1) < (unsigned)HH) ? 1.f : 0.f;
        float vx0 = ((unsigned)x0       < (unsigned)WW) ? 1.f : 0.f;
        float vx1 = ((unsigned)(x0 + 1) < (unsigned)WW) ? 1.f : 0.f;
        float a0 = (1.f - wy) * vy0, a1 = wy * vy1;
        float b0 = (1.f - wx) * vx0, b1 = wx * vx1;
        float w00 = a0 * b0, w01 = a0 * b1, w10 = a1 * b0, w11 = a1 * b1;
        int yc0 = min(max(y0, 0), HH - 1), yc1 = min(max(y0 + 1, 0), HH - 1);
        int xc0 = min(max(x0, 0), WW - 1), xc1 = min(max(x0 + 1, 0), WW - 1);
        int i00 = yc0 * WW + xc0, i01 = yc0 * WW + xc1;
        int i10 = yc1 * WW + xc0, i11 = yc1 * WW + xc1;
        u64 t01 = mul2(pack2(__ldg(p0 + i00), __ldg(p1 + i00)), rep2(w00));
        t01 = ffma2(pack2(__ldg(p0 + i01), __ldg(p1 + i01)), rep2(w01), t01);
        t01 = ffma2(pack2(__ldg(p0 + i10), __ldg(p1 + i10)), rep2(w10), t01);
        t01 = ffma2(pack2(__ldg(p0 + i11), __ldg(p1 + i11)), rep2(w11), t01);
        v01 = t01;
        v2 = fmaf(__ldg(p2 + i11), w11,
             fmaf(__ldg(p2 + i10), w10,
             fmaf(__ldg(p2 + i01), w01, __ldg(p2 + i00) * w00)));
    }
}

// Merged deform for the 2-pixel pair: A/B chains interleaved per tap k,
// einsum weights loaded once per k and shared by both pixels.
template<bool INTERIOR>
__device__ __forceinline__ void deform_pair(
    const u64* offA, const u64* offB, float fiA, float fj,
    int ybase, int xbase,
    const u64 (*tileP)[TW], const float (*tile2)[TW],
    const float* __restrict__ p0, const float* __restrict__ p1,
    const float* __restrict__ p2,
    float* rA, float* rB)
{
    u64 aP0 = 0, aP1 = 0, aP2 = 0, bP0 = 0, bP1 = 0, bP2 = 0;
    float a20 = CW[660], a21 = CW[661], a22 = CW[662];
    float b20 = a20, b21 = a21, b22 = a22;

    #pragma unroll
    for (int k = 0; k < 9; k++) {
        const int ky = k / 3, kx = k % 3;
        const float py0A = fiA + (float)ky;
        const float px0  = fj + (float)kx;

        u64 vA01, vB01; float vA2, vB2;
        sample1<INTERIOR>(offA[k], py0A,       px0, ybase, xbase, tileP, tile2, p0, p1, p2, vA01, vA2);
        sample1<INTERIOR>(offB[k], py0A + 1.f, px0, ybase, xbase, tileP, tile2, p0, p1, p2, vB01, vB2);

        ulonglong2 wp01 = ldc128(560 + k * 8);   // (o=0 pair, o=1 pair)
        u64 wp2 = ldc64(560 + k * 8 + 4);        // o=2 pair
        float ws0 = CW[632 + k * 3 + 0], ws1 = CW[632 + k * 3 + 1], ws2 = CW[632 + k * 3 + 2];

        aP0 = ffma2(vA01, wp01.x, aP0);  bP0 = ffma2(vB01, wp01.x, bP0);
        aP1 = ffma2(vA01, wp01.y, aP1);  bP1 = ffma2(vB01, wp01.y, bP1);
        aP2 = ffma2(vA01, wp2,    aP2);  bP2 = ffma2(vB01, wp2,    bP2);
        a20 = fmaf(vA2, ws0, a20);       b20 = fmaf(vB2, ws0, b20);
        a21 = fmaf(vA2, ws1, a21);       b21 = fmaf(vB2, ws1, b21);
        a22 = fmaf(vA2, ws2, a22);       b22 = fmaf(vB2, ws2, b22);
    }
    float2 r0 = unpack2(aP0), r1 = unpack2(aP1), r2 = unpack2(aP2);
    rA[0] = r0.x + r0.y + a20; rA[1] = r1.x + r1.y + a21; rA[2] = r2.x + r2.y + a22;
    float2 s0 = unpack2(bP0), s1 = unpack2(bP1), s2 = unpack2(bP2);
    rB[0] = s0.x + s0.y + b20; rB[1] = s1.x + s1.y + b21; rB[2] = s2.x + s2.y + b22;
}

__global__ __launch_bounds__(128, 4) void dcn_fused(
    const float* __restrict__ x, float* __restrict__ out)
{
    __shared__ u64   tileP[TH][TW];   // 7040 B
    __shared__ float tile2[TH][TW];   // 3520 B

    const int tx = threadIdx.x, ty = threadIdx.y;
    const int tid = ty * 32 + tx;
    const int i0 = blockIdx.y * 8, j0 = blockIdx.x * 32, b = blockIdx.z;
    const int ybase = i0 - RPAD, xbase = j0 - RPAD;

    const float* p0 = x + (size_t)b * 3 * HH * WW;
    const float* p1 = p0 + HH * WW;
    const float* p2 = p1 + HH * WW;

    // ---- Stage tile (border-clamped, x-coalesced) ----
    #pragma unroll
    for (int it = 0; it < 7; it++) {
        int idx = tid + it * 128;
        if (idx < TH * TW) {
            int r = idx / TW, q = idx % TW;
            int gy = min(max(ybase + r, 0), HH - 1);
            int gx = min(max(xbase + q, 0), WW - 1);
            int g = gy * WW + gx;
            tileP[r][q] = pack2(__ldg(p0 + g), __ldg(p1 + g));
            tile2[r][q] = __ldg(p2 + g);
        }
    }
    __syncthreads();

    const int j  = j0 + tx;
    const int iA = i0 + 2 * ty;
    if (j >= WO || iA >= HO) return;

    // ---- Offset conv for both pixels; each weight vector loaded ONCE ----
    u64 offA[9], offB[9];
    #pragma unroll
    for (int p = 0; p < 9; p++) { u64 bp = ldc64(540 + 2 * p); offA[p] = bp; offB[p] = bp; }

    const int lyA = 2 * ty + RPAD, lx = tx + RPAD;

    #pragma unroll
    for (int kx = 0; kx < 3; kx++) {
        u64 rp[4]; float r2[4];
        #pragma unroll
        for (int r = 0; r < 4; r++) { rp[r] = tileP[lyA + r][lx + kx]; r2[r] = tile2[lyA + r][lx + kx]; }
        #pragma unroll
        for (int ky = 0; ky < 3; ky++) {
            float2 fA = unpack2(rp[ky]);
            float2 fB = unpack2(rp[ky + 1]);
            #pragma unroll
            for (int c = 0; c < 3; c++) {
                const int jj = c * 9 + ky * 3 + kx;
                float xa = (c == 0) ? fA.x : (c == 1) ? fA.y : r2[ky];
                float xb = (c == 0) ? fB.x : (c == 1) ? fB.y : r2[ky + 1];
                u64 xa2 = rep2(xa), xb2 = rep2(xb);
                ulonglong2 v0 = ldc128(jj * 20 + 0);
                ulonglong2 v1 = ldc128(jj * 20 + 4);
                ulonglong2 v2 = ldc128(jj * 20 + 8);
                ulonglong2 v3 = ldc128(jj * 20 + 12);
                u64 p8 = ldc64(jj * 20 + 16);
                offA[0] = ffma2(xa2, v0.x, offA[0]); offB[0] = ffma2(xb2, v0.x, offB[0]);
                offA[1] = ffma2(xa2, v0.y, offA[1]); offB[1] = ffma2(xb2, v0.y, offB[1]);
                offA[2] = ffma2(xa2, v1.x, offA[2]); offB[2] = ffma2(xb2, v1.x, offB[2]);
                offA[3] = ffma2(xa2, v1.y, offA[3]); offB[3] = ffma2(xb2, v1.y, offB[3]);
                offA[4] = ffma2(xa2, v2.x, offA[4]); offB[4] = ffma2(xb2, v2.x, offB[4]);
                offA[5] = ffma2(xa2, v2.y, offA[5]); offB[5] = ffma2(xb2, v2.y, offB[5]);
                offA[6] = ffma2(xa2, v3.x, offA[6]); offB[6] = ffma2(xb2, v3.x, offB[6]);
                offA[7] = ffma2(xa2, v3.y, offA[7]); offB[7] = ffma2(xb2, v3.y, offB[7]);
                offA[8] = ffma2(xa2, p8,   offA[8]); offB[8] = ffma2(xb2, p8,   offB[8]);
            }
        }
    }

    // ---- Deform + einsum, specialized on block interiority (uniform branch) ----
    const bool interior = (ybase >= 0) & (ybase + TH <= HH) & (xbase >= 0) & (xbase + TW <= WW);
    float rA[3], rB[3];
    if (interior)
        deform_pair<true >(offA, offB, (float)iA, (float)j, ybase, xbase, tileP, tile2, p0, p1, p2, rA, rB);
    else
        deform_pair<false>(offA, offB, (float)iA, (float)j, ybase, xbase, tileP, tile2, p0, p1, p2, rA, rB);

    const size_t plane = (size_t)HO * WO;
    size_t pa = (size_t)b * 3 * plane + (size_t)iA * WO + j;
    out[pa]             = rA[0];
    out[pa + plane]     = rA[1];
    out[pa + 2 * plane] = rA[2];
    pa += WO;
    out[pa]             = rB[0];
    out[pa + plane]     = rB[1];
    out[pa + 2 * plane] = rB[2];
}

extern "C" void kernel_launch(void* const* d_in, const int* in_sizes, int n_in,
                              void* d_out, int out_size)
{
    const float* x      = (const float*)d_in[0];
    const float* conv_w = (const float*)d_in[1];
    const float* conv_b = (const float*)d_in[2];
    const float* dcn_w  = (const float*)d_in[3];
    const float* dcn_b  = (const float*)d_in[4];
    float* out = (float*)d_out;

    float* sp = nullptr;  void* cp = nullptr;
    cudaGetSymbolAddress((void**)&sp, d_scratch);
    cudaGetSymbolAddress(&cp, CW);

    repack<<<1, 544>>>(conv_w, conv_b, dcn_w, dcn_b, sp);
    cudaMemcpyAsync(cp, sp, 672 * sizeof(float), cudaMemcpyDeviceToDevice);

    dim3 blk(32, 4);
    dim3 grd((WO + 31) / 32, (HO + 7) / 8, 16);
    dcn_fused<<<grd, blk>>>(x, out);
}

// round 6
// speedup vs baseline: 1.2231x; 1.2231x over previous
#include <cuda_runtime.h>

#define HH 384
#define WW 384
#define HO 382
#define WO 382
#define RPAD 5
#define TH 20    /* 8 + 2 + 2*RPAD */
#define TW 44    /* 32 + 2 + 2*RPAD */

typedef unsigned long long u64;

// Constant layout (floats):
// [0,540)    cwp[27][20]: conv weight pairs, cwp[jj*20+2p] = (w[2p][jj], w[2p+1][jj])
// [540,558)  conv-bias pairs at 540+2p
// [560,632)  dcn (c0,c1) pairs: (dcn_w[o][0][k], dcn_w[o][1][k]) at 560+k*8+2o (k-major, padded)
// [632,659)  dcn c2: dcn_w[o][2][k] at 632+k*3+o
// [660,663)  dcn bias
// [664,673)  kyf[k] = float(k/3)
// [673,682)  kxf[k] = float(k%3)
__constant__ __align__(16) float CW[688];
__device__ __align__(16) float d_scratch[688];

__device__ __forceinline__ u64 ffma2(u64 a, u64 b, u64 c){
    u64 d; asm("fma.rn.f32x2 %0,%1,%2,%3;" : "=l"(d) : "l"(a), "l"(b), "l"(c)); return d;
}
__device__ __forceinline__ u64 mul2(u64 a, u64 b){
    u64 d; asm("mul.rn.f32x2 %0,%1,%2;" : "=l"(d) : "l"(a), "l"(b)); return d;
}
__device__ __forceinline__ u64 add2(u64 a, u64 b){
    u64 d; asm("add.rn.f32x2 %0,%1,%2;" : "=l"(d) : "l"(a), "l"(b)); return d;
}
__device__ __forceinline__ u64 rep2(float x){
    u64 r; asm("mov.b64 %0,{%1,%1};" : "=l"(r) : "f"(x)); return r;
}
__device__ __forceinline__ u64 pack2(float a, float b){
    u64 r; asm("mov.b64 %0,{%1,%2};" : "=l"(r) : "f"(a), "f"(b)); return r;
}
__device__ __forceinline__ float2 unpack2(u64 v){
    float2 f; asm("mov.b64 {%0,%1},%2;" : "=f"(f.x), "=f"(f.y) : "l"(v)); return f;
}
__device__ __forceinline__ u64 ldc64(int foff){
    return *reinterpret_cast<const u64*>(&CW[foff]);
}
__device__ __forceinline__ ulonglong2 ldc128(int foff){
    return *reinterpret_cast<const ulonglong2*>(&CW[foff]);
}

__global__ void repack(const float* __restrict__ cw, const float* __restrict__ cb,
                       const float* __restrict__ dw, const float* __restrict__ db,
                       float* __restrict__ s)
{
    int t = threadIdx.x;
    if (t < 486) { int o = t / 27, jj = t % 27; s[jj * 20 + o] = cw[t]; }
    else if (t < 504) { s[540 + (t - 486)] = cb[t - 486]; }
    else if (t < 531) {
        int i = t - 504; int o = i / 9, k = i % 9;
        s[560 + k * 8 + 2 * o + 0] = dw[o * 27 + 0 + k];
        s[560 + k * 8 + 2 * o + 1] = dw[o * 27 + 9 + k];
        s[632 + k * 3 + o]         = dw[o * 27 + 18 + k];
    }
    else if (t < 534) { s[660 + (t - 531)] = db[t - 531]; }
    else if (t < 543) { int k = t - 534; s[560 + k * 8 + 6] = 0.f; s[560 + k * 8 + 7] = 0.f; }
    else if (t < 552) { int k = t - 543; s[664 + k] = (float)(k / 3); s[673 + k] = (float)(k % 3); }
}

// Deform + einsum for ONE pixel. Rolled tap loop (I$-friendly).
// INTERIOR: staged tile fully inside image => in-window implies in-image (no masks).
template<bool INTERIOR>
__device__ __forceinline__ void deform_one(
    const u64* __restrict__ off, float fi, float fj, int ybase, int xbase,
    const u64 (*tileP)[TW], const float (*tile2)[TW],
    const float* __restrict__ p0, const float* __restrict__ p1,
    const float* __restrict__ p2,
    float* __restrict__ res)
{
    u64 accP0 = 0, accP1 = 0, accP2 = 0;
    float a20 = CW[660], a21 = CW[661], a22 = CW[662];

    #pragma unroll 3
    for (int k = 0; k < 9; k++) {
        u64 pyx = add2(off[k], pack2(fi + CW[664 + k], fj + CW[673 + k]));
        float2 q = unpack2(pyx);                    // (py, px)
        int y0 = __float2int_rd(q.x), x0 = __float2int_rd(q.y);
        float wy = q.x - (float)y0, wx = q.y - (float)x0;

        int ry = y0 - ybase, rx = x0 - xbase;
        bool inw = ((unsigned)ry < (unsigned)(TH - 1)) & ((unsigned)rx < (unsigned)(TW - 1));

        u64 v01; float v2;
        if (__builtin_expect(inw, 1)) {
            float a0, a1, b0, b1;
            if (INTERIOR) {
                a0 = 1.f - wy; a1 = wy; b0 = 1.f - wx; b1 = wx;
            } else {
                float vy0 = ((unsigned)y0       < (unsigned)HH) ? 1.f : 0.f;
                float vy1 = ((unsigned)(y0 + 1) < (unsigned)HH) ? 1.f : 0.f;
                float vx0 = ((unsigned)x0       < (unsigned)WW) ? 1.f : 0.f;
                float vx1 = ((unsigned)(x0 + 1) < (unsigned)WW) ? 1.f : 0.f;
                a0 = (1.f - wy) * vy0; a1 = wy * vy1;
                b0 = (1.f - wx) * vx0; b1 = wx * vx1;
            }
            float w00 = a0 * b0, w01 = a0 * b1, w10 = a1 * b0, w11 = a1 * b1;
            u64 t01 = mul2(tileP[ry][rx], rep2(w00));
            t01 = ffma2(tileP[ry][rx + 1],     rep2(w01), t01);
            t01 = ffma2(tileP[ry + 1][rx],     rep2(w10), t01);
            t01 = ffma2(tileP[ry + 1][rx + 1], rep2(w11), t01);
            v01 = t01;
            v2 = fmaf(tile2[ry + 1][rx + 1], w11,
                 fmaf(tile2[ry + 1][rx],     w10,
                 fmaf(tile2[ry][rx + 1],     w01, tile2[ry][rx] * w00)));
        } else {
            float vy0 = ((unsigned)y0       < (unsigned)HH) ? 1.f : 0.f;
            float vy1 = ((unsigned)(y0 + 1) < (unsigned)HH) ? 1.f : 0.f;
            float vx0 = ((unsigned)x0       < (unsigned)WW) ? 1.f : 0.f;
            float vx1 = ((unsigned)(x0 + 1) < (unsigned)WW) ? 1.f : 0.f;
            float a0 = (1.f - wy) * vy0, a1 = wy * vy1;
            float b0 = (1.f - wx) * vx0, b1 = wx * vx1;
            float w00 = a0 * b0, w01 = a0 * b1, w10 = a1 * b0, w11 = a1 * b1;
            int yc0 = min(max(y0, 0), HH - 1), yc1 = min(max(y0 + 1, 0), HH - 1);
            int xc0 = min(max(x0, 0), WW - 1), xc1 = min(max(x0 + 1, 0), WW - 1);
            int i00 = yc0 * WW + xc0, i01 = yc0 * WW + xc1;
            int i10 = yc1 * WW + xc0, i11 = yc1 * WW + xc1;
            u64 t01 = mul2(pack2(__ldg(p0 + i00), __ldg(p1 + i00)), rep2(w00));
            t01 = ffma2(pack2(__ldg(p0 + i01), __ldg(p1 + i01)), rep2(w01), t01);
            t01 = ffma2(pack2(__ldg(p0 + i10), __ldg(p1 + i10)), rep2(w10), t01);
            t01 = ffma2(pack2(__ldg(p0 + i11), __ldg(p1 + i11)), rep2(w11), t01);
            v01 = t01;
            v2 = fmaf(__ldg(p2 + i11), w11,
                 fmaf(__ldg(p2 + i10), w10,
                 fmaf(__ldg(p2 + i01), w01, __ldg(p2 + i00) * w00)));
        }

        ulonglong2 wp01 = ldc128(560 + k * 8);      // (o=0 pair, o=1 pair)
        u64 wp2 = ldc64(560 + k * 8 + 4);           // o=2 pair
        accP0 = ffma2(v01, wp01.x, accP0);
        accP1 = ffma2(v01, wp01.y, accP1);
        accP2 = ffma2(v01, wp2,    accP2);
        a20 = fmaf(v2, CW[632 + k * 3 + 0], a20);
        a21 = fmaf(v2, CW[632 + k * 3 + 1], a21);
        a22 = fmaf(v2, CW[632 + k * 3 + 2], a22);
    }
    float2 r0 = unpack2(accP0), r1 = unpack2(accP1), r2 = unpack2(accP2);
    res[0] = r0.x + r0.y + a20;
    res[1] = r1.x + r1.y + a21;
    res[2] = r2.x + r2.y + a22;
}

__global__ __launch_bounds__(128, 6) void dcn_fused(
    const float* __restrict__ x, float* __restrict__ out)
{
    __shared__ u64   tileP[TH][TW];   // 7040 B
    __shared__ float tile2[TH][TW];   // 3520 B

    const int tx = threadIdx.x, ty = threadIdx.y;
    const int tid = ty * 32 + tx;
    const int i0 = blockIdx.y * 8, j0 = blockIdx.x * 32, b = blockIdx.z;
    const int ybase = i0 - RPAD, xbase = j0 - RPAD;

    const float* p0 = x + (size_t)b * 3 * HH * WW;
    const float* p1 = p0 + HH * WW;
    const float* p2 = p1 + HH * WW;

    // ---- Stage tile (border-clamped, x-coalesced) ----
    #pragma unroll
    for (int it = 0; it < 7; it++) {
        int idx = tid + it * 128;
        if (idx < TH * TW) {
            int r = idx / TW, q = idx % TW;
            int gy = min(max(ybase + r, 0), HH - 1);
            int gx = min(max(xbase + q, 0), WW - 1);
            int g = gy * WW + gx;
            tileP[r][q] = pack2(__ldg(p0 + g), __ldg(p1 + g));
            tile2[r][q] = __ldg(p2 + g);
        }
    }
    __syncthreads();

    const int j  = j0 + tx;
    const int iA = i0 + 2 * ty;
    if (j >= WO || iA >= HO) return;

    // ---- Offset conv for both pixels; each weight vector loaded ONCE ----
    u64 offA[9], offB[9];
    #pragma unroll
    for (int p = 0; p < 9; p++) { u64 bp = ldc64(540 + 2 * p); offA[p] = bp; offB[p] = bp; }

    const int lyA = 2 * ty + RPAD, lx = tx + RPAD;

    #pragma unroll
    for (int kx = 0; kx < 3; kx++) {
        u64 rp[4]; float r2[4];
        #pragma unroll
        for (int r = 0; r < 4; r++) { rp[r] = tileP[lyA + r][lx + kx]; r2[r] = tile2[lyA + r][lx + kx]; }
        #pragma unroll
        for (int ky = 0; ky < 3; ky++) {
            float2 fA = unpack2(rp[ky]);
            float2 fB = unpack2(rp[ky + 1]);
            #pragma unroll
            for (int c = 0; c < 3; c++) {
                const int jj = c * 9 + ky * 3 + kx;
                float xa = (c == 0) ? fA.x : (c == 1) ? fA.y : r2[ky];
                float xb = (c == 0) ? fB.x : (c == 1) ? fB.y : r2[ky + 1];
                u64 xa2 = rep2(xa), xb2 = rep2(xb);
                ulonglong2 v0 = ldc128(jj * 20 + 0);
                ulonglong2 v1 = ldc128(jj * 20 + 4);
                ulonglong2 v2 = ldc128(jj * 20 + 8);
                ulonglong2 v3 = ldc128(jj * 20 + 12);
                u64 p8 = ldc64(jj * 20 + 16);
                offA[0] = ffma2(xa2, v0.x, offA[0]); offB[0] = ffma2(xb2, v0.x, offB[0]);
                offA[1] = ffma2(xa2, v0.y, offA[1]); offB[1] = ffma2(xb2, v0.y, offB[1]);
                offA[2] = ffma2(xa2, v1.x, offA[2]); offB[2] = ffma2(xb2, v1.x, offB[2]);
                offA[3] = ffma2(xa2, v1.y, offA[3]); offB[3] = ffma2(xb2, v1.y, offB[3]);
                offA[4] = ffma2(xa2, v2.x, offA[4]); offB[4] = ffma2(xb2, v2.x, offB[4]);
                offA[5] = ffma2(xa2, v2.y, offA[5]); offB[5] = ffma2(xb2, v2.y, offB[5]);
                offA[6] = ffma2(xa2, v3.x, offA[6]); offB[6] = ffma2(xb2, v3.x, offB[6]);
                offA[7] = ffma2(xa2, v3.y, offA[7]); offB[7] = ffma2(xb2, v3.y, offB[7]);
                offA[8] = ffma2(xa2, p8,   offA[8]); offB[8] = ffma2(xb2, p8,   offB[8]);
            }
        }
    }

    // ---- Deform + einsum; block-uniform interiority specialization ----
    const bool interior = (ybase >= 0) & (ybase + TH <= HH) & (xbase >= 0) & (xbase + TW <= WW);
    float rA[3], rB[3];
    const float fiA = (float)iA, fj = (float)j;
    if (interior) {
        deform_one<true >(offA, fiA,       fj, ybase, xbase, tileP, tile2, p0, p1, p2, rA);
        deform_one<true >(offB, fiA + 1.f, fj, ybase, xbase, tileP, tile2, p0, p1, p2, rB);
    } else {
        deform_one<false>(offA, fiA,       fj, ybase, xbase, tileP, tile2, p0, p1, p2, rA);
        deform_one<false>(offB, fiA + 1.f, fj, ybase, xbase, tileP, tile2, p0, p1, p2, rB);
    }

    const size_t plane = (size_t)HO * WO;
    size_t pa = (size_t)b * 3 * plane + (size_t)iA * WO + j;
    out[pa]             = rA[0];
    out[pa + plane]     = rA[1];
    out[pa + 2 * plane] = rA[2];
    pa += WO;
    out[pa]             = rB[0];
    out[pa + plane]     = rB[1];
    out[pa + 2 * plane] = rB[2];
}

extern "C" void kernel_launch(void* const* d_in, const int* in_sizes, int n_in,
                              void* d_out, int out_size)
{
    const float* x      = (const float*)d_in[0];
    const float* conv_w = (const float*)d_in[1];
    const float* conv_b = (const float*)d_in[2];
    const float* dcn_w  = (const float*)d_in[3];
    const float* dcn_b  = (const float*)d_in[4];
    float* out = (float*)d_out;

    float* sp = nullptr;  void* cp = nullptr;
    cudaGetSymbolAddress((void**)&sp, d_scratch);
    cudaGetSymbolAddress(&cp, CW);

    repack<<<1, 552>>>(conv_w, conv_b, dcn_w, dcn_b, sp);
    cudaMemcpyAsync(cp, sp, 688 * sizeof(float), cudaMemcpyDeviceToDevice);

    dim3 blk(32, 4);
    dim3 grd((WO + 31) / 32, (HO + 7) / 8, 16);
    dcn_fused<<<grd, blk>>>(x, out);
}